// round 4
// baseline (speedup 1.0000x reference)
#include <cuda_runtime.h>
#include <math.h>

// Problem constants (fixed by the dataset)
#define Bv 16
#define Tv 3072
#define Dv 256
#define GHv 32
#define GWv 32
#define Gv 1024
#define BT (Bv * Tv)          // 49152

// Output layout: concat of [som_z (BT*Dv)] [q (BT*Gv)] [bmu (BT)] [k_coord (BT*2)]
#define OFF_Q   ((size_t)BT * Dv)
#define OFF_BMU (OFF_Q + (size_t)BT * Gv)
#define OFF_KC  (OFF_BMU + (size_t)BT)

// Scratch (static device allocation — allowed; no cudaMalloc)
__device__ float g_wz[(size_t)BT * Dv];   // weighted z (time decay * mask)
__device__ float g_rown[BT];              // ||wz_row||^2
__device__ float g_nn[Gv];                // ||node||^2

// ---------------------------------------------------------------------------
// K0a: node squared norms. One block per node, 256 threads reduce D=256.
// ---------------------------------------------------------------------------
__global__ void k_node_norm(const float* __restrict__ nodes) {
    int g = blockIdx.x;
    int tid = threadIdx.x;
    float v = nodes[(size_t)g * Dv + tid];
    __shared__ float s[256];
    s[tid] = v * v;
    __syncthreads();
    for (int st = 128; st > 0; st >>= 1) {
        if (tid < st) s[tid] += s[tid + st];
        __syncthreads();
    }
    if (tid == 0) g_nn[g] = s[0];
}

// ---------------------------------------------------------------------------
// K0b: wz = z * decay^(T-1-t) * mask, plus row squared norms.
// CRITICAL: time weight computed as powf(0.999f, k) — f32 base, libdevice
// __nv_powf — to match the reference's f32 `0.999 ** arange(f32)` bitwise.
// ---------------------------------------------------------------------------
__global__ void k_prep(const float* __restrict__ z, const float* __restrict__ mask) {
    int r = blockIdx.x;
    int tid = threadIdx.x;
    __shared__ float s[256];
    __shared__ float s_tw;
    if (tid == 0) {
        int t = r % Tv;
        s_tw = powf(0.999f, (float)(Tv - 1 - t));
    }
    __syncthreads();
    float tw = s_tw;
    float m = mask[r];
    float w = (z[(size_t)r * Dv + tid] * tw) * m;
    g_wz[(size_t)r * Dv + tid] = w;
    s[tid] = w * w;
    __syncthreads();
    for (int st = 128; st > 0; st >>= 1) {
        if (tid < st) s[tid] += s[tid + st];
        __syncthreads();
    }
    if (tid == 0) g_rown[r] = s[0];
}

// ---------------------------------------------------------------------------
// K1: tiled fp32 SIMT GEMM: C[r,g] = dot(wz[r,:], nodes[g,:])   (NT)
// Block tile 64x64, K-chunks of 16, 256 threads, 4x4 micro-tile.
// Fused epilogue: u = 1/(1 + sqrt(max((rn - 2C) + nn, 1e-12))) written directly
// into the q region of d_out (unnormalized; K2 normalizes in place).
// ---------------------------------------------------------------------------
__global__ __launch_bounds__(256) void k_gemm(const float* __restrict__ nodes,
                                              float* __restrict__ out) {
    __shared__ float As[16][68];   // [k][m], padded
    __shared__ float Bs[16][68];   // [k][n]

    int tid = threadIdx.x;
    int tx = tid & 15;             // 0..15  -> n micro
    int ty = tid >> 4;             // 0..15  -> m micro
    int rowBase = blockIdx.x * 64;
    int colBase = blockIdx.y * 64;

    int lr   = tid >> 2;           // 0..63 tile row for loads
    int lseg = tid & 3;            // which float4 of the 16-wide k chunk

    const float* Ap = g_wz  + (size_t)(rowBase + lr) * Dv + lseg * 4;
    const float* Bp = nodes + (size_t)(colBase + lr) * Dv + lseg * 4;

    float acc[4][4];
#pragma unroll
    for (int i = 0; i < 4; i++)
#pragma unroll
        for (int j = 0; j < 4; j++) acc[i][j] = 0.f;

#pragma unroll 4
    for (int k0 = 0; k0 < Dv; k0 += 16) {
        float4 a = *(const float4*)(Ap + k0);
        float4 b = *(const float4*)(Bp + k0);
        As[lseg * 4 + 0][lr] = a.x;
        As[lseg * 4 + 1][lr] = a.y;
        As[lseg * 4 + 2][lr] = a.z;
        As[lseg * 4 + 3][lr] = a.w;
        Bs[lseg * 4 + 0][lr] = b.x;
        Bs[lseg * 4 + 1][lr] = b.y;
        Bs[lseg * 4 + 2][lr] = b.z;
        Bs[lseg * 4 + 3][lr] = b.w;
        __syncthreads();
#pragma unroll
        for (int k = 0; k < 16; k++) {
            float4 av = *(const float4*)&As[k][ty * 4];
            float4 bv = *(const float4*)&Bs[k][tx * 4];
            float af[4] = {av.x, av.y, av.z, av.w};
            float bf[4] = {bv.x, bv.y, bv.z, bv.w};
#pragma unroll
            for (int i = 0; i < 4; i++)
#pragma unroll
                for (int j = 0; j < 4; j++)
                    acc[i][j] = fmaf(af[i], bf[j], acc[i][j]);
        }
        __syncthreads();
    }

    float* q = out + OFF_Q;
    float nn[4];
#pragma unroll
    for (int j = 0; j < 4; j++) nn[j] = g_nn[colBase + tx * 4 + j];

#pragma unroll
    for (int i = 0; i < 4; i++) {
        int row = rowBase + ty * 4 + i;
        float rn = g_rown[row];
        float4 o;
        float* op = &o.x;
#pragma unroll
        for (int j = 0; j < 4; j++) {
            float d2 = fmaxf((rn - 2.f * acc[i][j]) + nn[j], 1e-12f);
            op[j] = 1.f / (1.f + sqrtf(d2));
        }
        *(float4*)(q + (size_t)row * Gv + colBase + tx * 4) = o;
    }
}

// ---------------------------------------------------------------------------
// K2: per-row pass. One block per row, 256 threads.
// Reads unnormalized u (4 floats/thread), reduces sum + argmax (tie -> lowest
// index, matching jnp argmin over dist), normalizes q in place, writes
// som_z / bmu / k_coord.
// ---------------------------------------------------------------------------
__global__ __launch_bounds__(256) void k_row(const float* __restrict__ z,
                                             const float* __restrict__ mask,
                                             const float* __restrict__ nodes,
                                             float* __restrict__ out) {
    int r = blockIdx.x;
    int tid = threadIdx.x;
    float* qptr = out + OFF_Q + (size_t)r * Gv;

    float4 u4 = ((const float4*)qptr)[tid];
    float lsum = u4.x + u4.y + u4.z + u4.w;
    // local argmax over 4, ties resolved to lowest index by strict > ordering
    float bv = u4.x; int bi = tid * 4;
    if (u4.y > bv) { bv = u4.y; bi = tid * 4 + 1; }
    if (u4.z > bv) { bv = u4.z; bi = tid * 4 + 2; }
    if (u4.w > bv) { bv = u4.w; bi = tid * 4 + 3; }

    __shared__ float sSum[256];
    __shared__ float sV[256];
    __shared__ int   sI[256];
    sSum[tid] = lsum; sV[tid] = bv; sI[tid] = bi;
    __syncthreads();
    for (int st = 128; st > 0; st >>= 1) {
        if (tid < st) {
            sSum[tid] += sSum[tid + st];
            float ov = sV[tid + st]; int oi = sI[tid + st];
            if (ov > sV[tid] || (ov == sV[tid] && oi < sI[tid])) {
                sV[tid] = ov; sI[tid] = oi;
            }
        }
        __syncthreads();
    }
    float inv = 1.f / sSum[0];
    int bmu = sI[0];
    __syncthreads();

    u4.x *= inv; u4.y *= inv; u4.z *= inv; u4.w *= inv;
    ((float4*)qptr)[tid] = u4;

    // som_z: each thread handles one d
    float zz = z[(size_t)r * Dv + tid];
    float m = mask[r];
    float nv = nodes[(size_t)bmu * Dv + tid];
    out[(size_t)r * Dv + tid] = zz + 0.1f * (nv - zz) * m;

    if (tid == 0) {
        out[OFF_BMU + r] = (float)bmu;
        float* kc = out + OFF_KC;
        kc[(size_t)r * 2 + 0] = (float)(bmu / GWv);
        kc[(size_t)r * 2 + 1] = (float)(bmu % GWv);
    }
}

// ---------------------------------------------------------------------------
extern "C" void kernel_launch(void* const* d_in, const int* in_sizes, int n_in,
                              void* d_out, int out_size) {
    (void)in_sizes; (void)n_in; (void)out_size;
    const float* z     = (const float*)d_in[0];
    const float* mask  = (const float*)d_in[1];
    const float* nodes = (const float*)d_in[2];
    float* out = (float*)d_out;

    k_node_norm<<<Gv, 256>>>(nodes);
    k_prep<<<BT, 256>>>(z, mask);
    dim3 grid(BT / 64, Gv / 64);
    k_gemm<<<grid, 256>>>(nodes, out);
    k_row<<<BT, 256>>>(z, mask, nodes, out);
}

// round 5
// speedup vs baseline: 1.0013x; 1.0013x over previous
#include <cuda_runtime.h>
#include <math.h>

// Problem constants (fixed by the dataset)
#define Bv 16
#define Tv 3072
#define Dv 256
#define GHv 32
#define GWv 32
#define Gv 1024
#define BT (Bv * Tv)          // 49152

// Output layout: concat of [som_z (BT*Dv)] [q (BT*Gv)] [bmu (BT)] [k_coord (BT*2)]
#define OFF_Q   ((size_t)BT * Dv)
#define OFF_BMU (OFF_Q + (size_t)BT * Gv)
#define OFF_KC  (OFF_BMU + (size_t)BT)

// Scratch (static device allocation — allowed; no cudaMalloc)
__device__ float g_wz[(size_t)BT * Dv];   // weighted z (time decay * mask)
__device__ float g_rown[BT];              // ||wz_row||^2
__device__ float g_nn[Gv];                // ||node||^2

// ---------------------------------------------------------------------------
// K0a: node squared norms. One block per node, 256 threads reduce D=256.
// ---------------------------------------------------------------------------
__global__ void k_node_norm(const float* __restrict__ nodes) {
    int g = blockIdx.x;
    int tid = threadIdx.x;
    float v = nodes[(size_t)g * Dv + tid];
    __shared__ float s[256];
    s[tid] = v * v;
    __syncthreads();
    for (int st = 128; st > 0; st >>= 1) {
        if (tid < st) s[tid] += s[tid + st];
        __syncthreads();
    }
    if (tid == 0) g_nn[g] = s[0];
}

// ---------------------------------------------------------------------------
// K0b: wz = z * decay^(T-1-t) * mask, plus row squared norms.
// CRITICAL: time weight computed as powf(0.999f, k) — f32 base, libdevice
// __nv_powf — to match the reference's f32 `0.999 ** arange(f32)` bitwise.
// ---------------------------------------------------------------------------
__global__ void k_prep(const float* __restrict__ z, const float* __restrict__ mask) {
    int r = blockIdx.x;
    int tid = threadIdx.x;
    __shared__ float s[256];
    __shared__ float s_tw;
    if (tid == 0) {
        int t = r % Tv;
        s_tw = powf(0.999f, (float)(Tv - 1 - t));
    }
    __syncthreads();
    float tw = s_tw;
    float m = mask[r];
    float w = (z[(size_t)r * Dv + tid] * tw) * m;
    g_wz[(size_t)r * Dv + tid] = w;
    s[tid] = w * w;
    __syncthreads();
    for (int st = 128; st > 0; st >>= 1) {
        if (tid < st) s[tid] += s[tid + st];
        __syncthreads();
    }
    if (tid == 0) g_rown[r] = s[0];
}

// ---------------------------------------------------------------------------
// K1: tiled fp32 SIMT GEMM: C[r,g] = dot(wz[r,:], nodes[g,:])   (NT)
// Block tile 64x64, K-chunks of 16, 256 threads, 4x4 micro-tile.
// Fused epilogue: u = 1/(1 + sqrt(max((rn - 2C) + nn, 1e-12))) written directly
// into the q region of d_out (unnormalized; K2 normalizes in place).
// ---------------------------------------------------------------------------
__global__ __launch_bounds__(256) void k_gemm(const float* __restrict__ nodes,
                                              float* __restrict__ out) {
    __shared__ float As[16][68];   // [k][m], padded
    __shared__ float Bs[16][68];   // [k][n]

    int tid = threadIdx.x;
    int tx = tid & 15;             // 0..15  -> n micro
    int ty = tid >> 4;             // 0..15  -> m micro
    int rowBase = blockIdx.x * 64;
    int colBase = blockIdx.y * 64;

    int lr   = tid >> 2;           // 0..63 tile row for loads
    int lseg = tid & 3;            // which float4 of the 16-wide k chunk

    const float* Ap = g_wz  + (size_t)(rowBase + lr) * Dv + lseg * 4;
    const float* Bp = nodes + (size_t)(colBase + lr) * Dv + lseg * 4;

    float acc[4][4];
#pragma unroll
    for (int i = 0; i < 4; i++)
#pragma unroll
        for (int j = 0; j < 4; j++) acc[i][j] = 0.f;

#pragma unroll 4
    for (int k0 = 0; k0 < Dv; k0 += 16) {
        float4 a = *(const float4*)(Ap + k0);
        float4 b = *(const float4*)(Bp + k0);
        As[lseg * 4 + 0][lr] = a.x;
        As[lseg * 4 + 1][lr] = a.y;
        As[lseg * 4 + 2][lr] = a.z;
        As[lseg * 4 + 3][lr] = a.w;
        Bs[lseg * 4 + 0][lr] = b.x;
        Bs[lseg * 4 + 1][lr] = b.y;
        Bs[lseg * 4 + 2][lr] = b.z;
        Bs[lseg * 4 + 3][lr] = b.w;
        __syncthreads();
#pragma unroll
        for (int k = 0; k < 16; k++) {
            float4 av = *(const float4*)&As[k][ty * 4];
            float4 bv = *(const float4*)&Bs[k][tx * 4];
            float af[4] = {av.x, av.y, av.z, av.w};
            float bf[4] = {bv.x, bv.y, bv.z, bv.w};
#pragma unroll
            for (int i = 0; i < 4; i++)
#pragma unroll
                for (int j = 0; j < 4; j++)
                    acc[i][j] = fmaf(af[i], bf[j], acc[i][j]);
        }
        __syncthreads();
    }

    float* q = out + OFF_Q;
    float nn[4];
#pragma unroll
    for (int j = 0; j < 4; j++) nn[j] = g_nn[colBase + tx * 4 + j];

#pragma unroll
    for (int i = 0; i < 4; i++) {
        int row = rowBase + ty * 4 + i;
        float rn = g_rown[row];
        float4 o;
        float* op = &o.x;
#pragma unroll
        for (int j = 0; j < 4; j++) {
            float d2 = fmaxf((rn - 2.f * acc[i][j]) + nn[j], 1e-12f);
            op[j] = 1.f / (1.f + sqrtf(d2));
        }
        *(float4*)(q + (size_t)row * Gv + colBase + tx * 4) = o;
    }
}

// ---------------------------------------------------------------------------
// K2: per-row pass. One block per row, 256 threads.
// Reads unnormalized u (4 floats/thread), reduces sum + argmax (tie -> lowest
// index, matching jnp argmin over dist), normalizes q in place, writes
// som_z / bmu / k_coord.
// ---------------------------------------------------------------------------
__global__ __launch_bounds__(256) void k_row(const float* __restrict__ z,
                                             const float* __restrict__ mask,
                                             const float* __restrict__ nodes,
                                             float* __restrict__ out) {
    int r = blockIdx.x;
    int tid = threadIdx.x;
    float* qptr = out + OFF_Q + (size_t)r * Gv;

    float4 u4 = ((const float4*)qptr)[tid];
    float lsum = u4.x + u4.y + u4.z + u4.w;
    // local argmax over 4, ties resolved to lowest index by strict > ordering
    float bv = u4.x; int bi = tid * 4;
    if (u4.y > bv) { bv = u4.y; bi = tid * 4 + 1; }
    if (u4.z > bv) { bv = u4.z; bi = tid * 4 + 2; }
    if (u4.w > bv) { bv = u4.w; bi = tid * 4 + 3; }

    __shared__ float sSum[256];
    __shared__ float sV[256];
    __shared__ int   sI[256];
    sSum[tid] = lsum; sV[tid] = bv; sI[tid] = bi;
    __syncthreads();
    for (int st = 128; st > 0; st >>= 1) {
        if (tid < st) {
            sSum[tid] += sSum[tid + st];
            float ov = sV[tid + st]; int oi = sI[tid + st];
            if (ov > sV[tid] || (ov == sV[tid] && oi < sI[tid])) {
                sV[tid] = ov; sI[tid] = oi;
            }
        }
        __syncthreads();
    }
    float inv = 1.f / sSum[0];
    int bmu = sI[0];
    __syncthreads();

    u4.x *= inv; u4.y *= inv; u4.z *= inv; u4.w *= inv;
    ((float4*)qptr)[tid] = u4;

    // som_z: each thread handles one d
    float zz = z[(size_t)r * Dv + tid];
    float m = mask[r];
    float nv = nodes[(size_t)bmu * Dv + tid];
    out[(size_t)r * Dv + tid] = zz + 0.1f * (nv - zz) * m;

    if (tid == 0) {
        out[OFF_BMU + r] = (float)bmu;
        float* kc = out + OFF_KC;
        kc[(size_t)r * 2 + 0] = (float)(bmu / GWv);
        kc[(size_t)r * 2 + 1] = (float)(bmu % GWv);
    }
}

// ---------------------------------------------------------------------------
extern "C" void kernel_launch(void* const* d_in, const int* in_sizes, int n_in,
                              void* d_out, int out_size) {
    (void)in_sizes; (void)n_in; (void)out_size;
    const float* z     = (const float*)d_in[0];
    const float* mask  = (const float*)d_in[1];
    const float* nodes = (const float*)d_in[2];
    float* out = (float*)d_out;

    k_node_norm<<<Gv, 256>>>(nodes);
    k_prep<<<BT, 256>>>(z, mask);
    dim3 grid(BT / 64, Gv / 64);
    k_gemm<<<grid, 256>>>(nodes, out);
    k_row<<<BT, 256>>>(z, mask, nodes, out);
}

// round 7
// speedup vs baseline: 1.9635x; 1.9609x over previous
#include <cuda_runtime.h>
#include <math.h>
#include <stdint.h>

// Problem constants (fixed by the dataset)
#define Bv 16
#define Tv 3072
#define Dv 256
#define GHv 32
#define GWv 32
#define Gv 1024
#define BT (Bv * Tv)          // 49152

// Output layout: concat of [som_z (BT*Dv)] [q (BT*Gv)] [bmu (BT)] [k_coord (BT*2)]
#define OFF_Q   ((size_t)BT * Dv)
#define OFF_BMU (OFF_Q + (size_t)BT * Gv)
#define OFF_KC  (OFF_BMU + (size_t)BT)

// Exact-argmin refinement margin (dist units) and candidate cap
#define REFINE_MARGIN 6e-3f
#define MAX_CAND 32

// Scratch (static device allocation — allowed; no cudaMalloc)
__device__ float g_wz[(size_t)BT * Dv];   // weighted z (time decay * mask)
__device__ float g_rown[BT];              // ||wz_row||^2
__device__ float g_nn[Gv];                // ||node||^2

// ---------------------------------------------------------------------------
// helpers
// ---------------------------------------------------------------------------
__device__ __forceinline__ float tf32r(float x) {
    uint32_t o;
    asm("cvt.rna.tf32.f32 %0, %1;" : "=r"(o) : "f"(x));
    return __uint_as_float(o);
}

__device__ __forceinline__ void mma8(float* c, const float* a, const float* b) {
    asm volatile(
        "mma.sync.aligned.m16n8k8.row.col.f32.tf32.tf32.f32 "
        "{%0,%1,%2,%3}, {%4,%5,%6,%7}, {%8,%9}, {%0,%1,%2,%3};"
        : "+f"(c[0]), "+f"(c[1]), "+f"(c[2]), "+f"(c[3])
        : "r"(__float_as_uint(a[0])), "r"(__float_as_uint(a[1])),
          "r"(__float_as_uint(a[2])), "r"(__float_as_uint(a[3])),
          "r"(__float_as_uint(b[0])), "r"(__float_as_uint(b[1])));
}

// ---------------------------------------------------------------------------
// K0a: node squared norms.
// ---------------------------------------------------------------------------
__global__ void k_node_norm(const float* __restrict__ nodes) {
    int g = blockIdx.x;
    int tid = threadIdx.x;
    float v = nodes[(size_t)g * Dv + tid];
    __shared__ float s[256];
    s[tid] = v * v;
    __syncthreads();
    for (int st = 128; st > 0; st >>= 1) {
        if (tid < st) s[tid] += s[tid + st];
        __syncthreads();
    }
    if (tid == 0) g_nn[g] = s[0];
}

// ---------------------------------------------------------------------------
// K0b: wz = z * decay^(T-1-t) * mask, plus row squared norms.
// Time weight via powf(0.999f, k) — matches reference's f32 power bitwise.
// ---------------------------------------------------------------------------
__global__ void k_prep(const float* __restrict__ z, const float* __restrict__ mask) {
    int r = blockIdx.x;
    int tid = threadIdx.x;
    __shared__ float s[256];
    __shared__ float s_tw;
    if (tid == 0) {
        int t = r % Tv;
        s_tw = powf(0.999f, (float)(Tv - 1 - t));
    }
    __syncthreads();
    float tw = s_tw;
    float m = mask[r];
    float w = (z[(size_t)r * Dv + tid] * tw) * m;
    g_wz[(size_t)r * Dv + tid] = w;
    s[tid] = w * w;
    __syncthreads();
    for (int st = 128; st > 0; st >>= 1) {
        if (tid < st) s[tid] += s[tid + st];
        __syncthreads();
    }
    if (tid == 0) g_rown[r] = s[0];
}

// ---------------------------------------------------------------------------
// K1: tf32 tensor-core GEMM  C[r,g] = dot(wz[r,:], nodes[g,:])   (NT)
// BM=128, BN=64, BK=32, 256 threads = 8 warps (4 M x 2 N), warp tile 32x32.
// Fused epilogue writes unnormalized u = 1/(1+sqrt(d2)) into q region.
// ---------------------------------------------------------------------------
__global__ __launch_bounds__(256, 2) void k_gemm_tc(const float* __restrict__ nodes,
                                                    float* __restrict__ out) {
    __shared__ float sA[128 * 36];   // [row][k], stride 36 (bank-friendly)
    __shared__ float sB[64 * 36];    // [n][k]
    __shared__ float s_rn[128];
    __shared__ float s_nn[64];

    int tid = threadIdx.x;
    int rowBase = blockIdx.x * 128;
    int colBase = blockIdx.y * 64;

    int lr  = tid >> 3;            // 0..31
    int lc4 = (tid & 7) * 4;       // 0,4,...,28

    const float* Ap = g_wz  + (size_t)(rowBase + lr) * Dv + lc4;
    const float* Bp = nodes + (size_t)(colBase + lr) * Dv + lc4;

    int lane = tid & 31, g4 = lane >> 2, tg = lane & 3;
    int wid = tid >> 5, wm = wid & 3, wn = wid >> 2;

    float acc[2][4][4];
#pragma unroll
    for (int mi = 0; mi < 2; mi++)
#pragma unroll
        for (int ni = 0; ni < 4; ni++)
#pragma unroll
            for (int k = 0; k < 4; k++) acc[mi][ni][k] = 0.f;

    float4 pa[4], pb[2];
#pragma unroll
    for (int i = 0; i < 4; i++) pa[i] = *(const float4*)(Ap + (size_t)i * 32 * Dv);
#pragma unroll
    for (int i = 0; i < 2; i++) pb[i] = *(const float4*)(Bp + (size_t)i * 32 * Dv);

    for (int ch = 0; ch < 8; ch++) {
        // convert + stage to smem
#pragma unroll
        for (int i = 0; i < 4; i++) {
            float4 t;
            t.x = tf32r(pa[i].x); t.y = tf32r(pa[i].y);
            t.z = tf32r(pa[i].z); t.w = tf32r(pa[i].w);
            *(float4*)&sA[(i * 32 + lr) * 36 + lc4] = t;
        }
#pragma unroll
        for (int i = 0; i < 2; i++) {
            float4 t;
            t.x = tf32r(pb[i].x); t.y = tf32r(pb[i].y);
            t.z = tf32r(pb[i].z); t.w = tf32r(pb[i].w);
            *(float4*)&sB[(i * 32 + lr) * 36 + lc4] = t;
        }
        __syncthreads();

        if (ch < 7) {
            const float* Ap2 = Ap + (ch + 1) * 32;
            const float* Bp2 = Bp + (ch + 1) * 32;
#pragma unroll
            for (int i = 0; i < 4; i++) pa[i] = *(const float4*)(Ap2 + (size_t)i * 32 * Dv);
#pragma unroll
            for (int i = 0; i < 2; i++) pb[i] = *(const float4*)(Bp2 + (size_t)i * 32 * Dv);
        }

#pragma unroll
        for (int kk = 0; kk < 4; kk++) {
            int kb = kk * 8;
            float af[2][4];
#pragma unroll
            for (int mi = 0; mi < 2; mi++) {
                int r0 = wm * 32 + mi * 16 + g4;
                af[mi][0] = sA[(r0)     * 36 + kb + tg];
                af[mi][1] = sA[(r0 + 8) * 36 + kb + tg];
                af[mi][2] = sA[(r0)     * 36 + kb + tg + 4];
                af[mi][3] = sA[(r0 + 8) * 36 + kb + tg + 4];
            }
            float bf[4][2];
#pragma unroll
            for (int ni = 0; ni < 4; ni++) {
                int n0 = wn * 32 + ni * 8 + g4;
                bf[ni][0] = sB[n0 * 36 + kb + tg];
                bf[ni][1] = sB[n0 * 36 + kb + tg + 4];
            }
#pragma unroll
            for (int mi = 0; mi < 2; mi++)
#pragma unroll
                for (int ni = 0; ni < 4; ni++)
                    mma8(acc[mi][ni], af[mi], bf[ni]);
        }
        __syncthreads();
    }

    // stage norms
    if (tid < 128) s_rn[tid] = g_rown[rowBase + tid];
    if (tid < 64)  s_nn[tid] = g_nn[colBase + tid];
    __syncthreads();

    float* q = out + OFF_Q;
#pragma unroll
    for (int mi = 0; mi < 2; mi++) {
#pragma unroll
        for (int h = 0; h < 2; h++) {
            int r = wm * 32 + mi * 16 + g4 + h * 8;
            float rn = s_rn[r];
            size_t grow = (size_t)(rowBase + r) * Gv + colBase;
#pragma unroll
            for (int ni = 0; ni < 4; ni++) {
                int c = wn * 32 + ni * 8 + tg * 2;
                float c0 = acc[mi][ni][h * 2 + 0];
                float c1 = acc[mi][ni][h * 2 + 1];
                float d20 = fmaxf((rn - 2.f * c0) + s_nn[c],     1e-12f);
                float d21 = fmaxf((rn - 2.f * c1) + s_nn[c + 1], 1e-12f);
                float2 o;
                o.x = 1.f / (1.f + sqrtf(d20));
                o.y = 1.f / (1.f + sqrtf(d21));
                *(float2*)(q + grow + c) = o;
            }
        }
    }
}

// ---------------------------------------------------------------------------
// K2: per-row pass. One block per row, 256 threads.
// Warp-shuffle sum + argmax; exact fp64 refinement of argmin for near-ties
// (required: tf32 GEMM noise can flip sub-1e-3 dist gaps, and a single flip
// fails the bmu tolerance).
// ---------------------------------------------------------------------------
__global__ __launch_bounds__(256) void k_row(const float* __restrict__ z,
                                             const float* __restrict__ mask,
                                             const float* __restrict__ nodes,
                                             float* __restrict__ out) {
    int r = blockIdx.x;
    int tid = threadIdx.x;
    int lane = tid & 31, warp = tid >> 5;
    float* qptr = out + OFF_Q + (size_t)r * Gv;

    float4 u4 = ((const float4*)qptr)[tid];
    float4 uo = u4;
    float lsum = (u4.x + u4.y) + (u4.z + u4.w);
    float bv = u4.x; int bi = tid * 4;
    if (u4.y > bv) { bv = u4.y; bi = tid * 4 + 1; }
    if (u4.z > bv) { bv = u4.z; bi = tid * 4 + 2; }
    if (u4.w > bv) { bv = u4.w; bi = tid * 4 + 3; }

    // warp butterfly: sum + argmax (tie -> lowest index)
#pragma unroll
    for (int off = 16; off > 0; off >>= 1) {
        float os = __shfl_xor_sync(0xFFFFFFFFu, lsum, off);
        float ov = __shfl_xor_sync(0xFFFFFFFFu, bv, off);
        int   oi = __shfl_xor_sync(0xFFFFFFFFu, bi, off);
        lsum += os;
        if (ov > bv || (ov == bv && oi < bi)) { bv = ov; bi = oi; }
    }

    __shared__ float sWs[8], sWv[8];
    __shared__ int   sWi[8];
    __shared__ float sSum, sMax;
    __shared__ int   sBmu;
    if (lane == 0) { sWs[warp] = lsum; sWv[warp] = bv; sWi[warp] = bi; }
    __syncthreads();
    if (tid == 0) {
        float ts = 0.f, tv = -1.f; int ti = 0;
#pragma unroll
        for (int w = 0; w < 8; w++) {
            ts += sWs[w];
            if (sWv[w] > tv || (sWv[w] == tv && sWi[w] < ti)) { tv = sWv[w]; ti = sWi[w]; }
        }
        sSum = ts; sMax = tv; sBmu = ti;
    }
    __syncthreads();
    float inv = 1.f / sSum;
    float umax = sMax;
    int bmu = sBmu;

    // normalize q in place
    u4.x *= inv; u4.y *= inv; u4.z *= inv; u4.w *= inv;
    ((float4*)qptr)[tid] = u4;

    // ---- exact argmin refinement for near-ties ----
    float dist1 = 1.f / umax - 1.f;
    float ut = 1.f / (1.f + dist1 + REFINE_MARGIN);

    __shared__ int sCand[MAX_CAND];
    __shared__ int sCnt;
    __shared__ double sD[256];
    __shared__ double sBest;
    if (tid == 0) sCnt = 0;
    __syncthreads();
    {
        float uu[4] = {uo.x, uo.y, uo.z, uo.w};
#pragma unroll
        for (int j = 0; j < 4; j++) {
            if (uu[j] >= ut) {
                int slot = atomicAdd(&sCnt, 1);
                if (slot < MAX_CAND) sCand[slot] = tid * 4 + j;
            }
        }
    }
    __syncthreads();
    int ncand = sCnt < MAX_CAND ? sCnt : MAX_CAND;

    if (ncand > 1) {
        float wzv = g_wz[(size_t)r * Dv + tid];
        double bestd = 1e300;
        int besti = Gv;
        for (int c = 0; c < ncand; c++) {
            int g = sCand[c];
            double diff = (double)wzv - (double)nodes[(size_t)g * Dv + tid];
            sD[tid] = diff * diff;
            __syncthreads();
            for (int st = 128; st > 0; st >>= 1) {
                if (tid < st) sD[tid] += sD[tid + st];
                __syncthreads();
            }
            if (tid == 0) sBest = sD[0];
            __syncthreads();
            double d2c = sBest;
            if (d2c < bestd || (d2c == bestd && g < besti)) { bestd = d2c; besti = g; }
            __syncthreads();
        }
        bmu = besti;
    }

    // som_z
    float zz = z[(size_t)r * Dv + tid];
    float m = mask[r];
    float nv = nodes[(size_t)bmu * Dv + tid];
    out[(size_t)r * Dv + tid] = zz + 0.1f * (nv - zz) * m;

    if (tid == 0) {
        out[OFF_BMU + r] = (float)bmu;
        float* kc = out + OFF_KC;
        kc[(size_t)r * 2 + 0] = (float)(bmu / GWv);
        kc[(size_t)r * 2 + 1] = (float)(bmu % GWv);
    }
}

// ---------------------------------------------------------------------------
extern "C" void kernel_launch(void* const* d_in, const int* in_sizes, int n_in,
                              void* d_out, int out_size) {
    (void)in_sizes; (void)n_in; (void)out_size;
    const float* z     = (const float*)d_in[0];
    const float* mask  = (const float*)d_in[1];
    const float* nodes = (const float*)d_in[2];
    float* out = (float*)d_out;

    k_node_norm<<<Gv, 256>>>(nodes);
    k_prep<<<BT, 256>>>(z, mask);
    dim3 grid(BT / 128, Gv / 64);
    k_gemm_tc<<<grid, 256>>>(nodes, out);
    k_row<<<BT, 256>>>(z, mask, nodes, out);
}

// round 9
// speedup vs baseline: 2.3994x; 1.2220x over previous
#include <cuda_runtime.h>
#include <math.h>
#include <stdint.h>

// Problem constants (fixed by the dataset)
#define Bv 16
#define Tv 3072
#define Dv 256
#define GHv 32
#define GWv 32
#define Gv 1024
#define BT (Bv * Tv)          // 49152

// Output layout: concat of [som_z (BT*Dv)] [q (BT*Gv)] [bmu (BT)] [k_coord (BT*2)]
#define OFF_Q   ((size_t)BT * Dv)
#define OFF_BMU (OFF_Q + (size_t)BT * Gv)
#define OFF_KC  (OFF_BMU + (size_t)BT)

// Exact-argmin refinement margin (dist units) and candidate cap.
// bf16 GEMM noise sigma(dist) ~ 1.7e-3; margin = ~9 sigma.
#define REFINE_MARGIN 1.5e-2f
#define MAX_CAND 64

// GEMM tiling: BM=128, BN=64, K chunks of 32
#define KCH 32
#define NCHUNK (Dv / KCH)      // 8

// Scratch (static device allocation — allowed; no cudaMalloc)
__device__ float g_wz[(size_t)BT * Dv];   // weighted z (time decay * mask)
__device__ float g_rown[BT];              // ||wz_row||^2
__device__ float g_nn[Gv];                // ||node||^2

// ---------------------------------------------------------------------------
// helpers
// ---------------------------------------------------------------------------
__device__ __forceinline__ uint32_t bfpack(float lo, float hi) {
    // word = {lo half = lo, hi half = hi}; cvt.bf16x2 takes (hi, lo)
    uint32_t r;
    asm("cvt.rn.bf16x2.f32 %0, %1, %2;" : "=r"(r) : "f"(hi), "f"(lo));
    return r;
}

__device__ __forceinline__ void mma16(float* c, const uint32_t* a,
                                      uint32_t b0, uint32_t b1) {
    asm volatile(
        "mma.sync.aligned.m16n8k16.row.col.f32.bf16.bf16.f32 "
        "{%0,%1,%2,%3}, {%4,%5,%6,%7}, {%8,%9}, {%0,%1,%2,%3};"
        : "+f"(c[0]), "+f"(c[1]), "+f"(c[2]), "+f"(c[3])
        : "r"(a[0]), "r"(a[1]), "r"(a[2]), "r"(a[3]), "r"(b0), "r"(b1));
}

// Fragment-major word index for A (128 rows x 16 kpairs per chunk).
// Consumer float4 at ((wm*2+mi)*2+kk)*128 + g4*16 + tg*4 yields a0..a3.
__device__ __forceinline__ int aIdx(int row, int p) {
    int wm = row >> 5, mi = (row >> 4) & 1, hi = (row >> 3) & 1, g4 = row & 7;
    int kk = p >> 3, w8 = p & 7, tg = w8 & 3, poff = w8 >> 2;
    return (((wm * 2 + mi) * 2 + kk) * 128) + g4 * 16 + tg * 4 + poff * 2 + hi;
}

// Fragment-major word index for B (64 n x 16 kpairs per chunk).
// Consumer float4 at (wn*2+kk)*256 + nh*128 + g4*16 + tg*4 yields
// {bf[2nh][0], bf[2nh][1], bf[2nh+1][0], bf[2nh+1][1]}.
__device__ __forceinline__ int bIdx(int n, int p) {
    int wn = n >> 5, ni = (n >> 3) & 3, g4 = n & 7;
    int nh = ni >> 1, nl = ni & 1;
    int kk = p >> 3, w8 = p & 7, tg = w8 & 3, b01 = w8 >> 2;
    return ((wn * 2 + kk) * 256) + nh * 128 + g4 * 16 + tg * 4 + nl * 2 + b01;
}

// ---------------------------------------------------------------------------
// K0a: node squared norms.
// ---------------------------------------------------------------------------
__global__ void k_node_norm(const float* __restrict__ nodes) {
    int g = blockIdx.x;
    int tid = threadIdx.x;
    float v = nodes[(size_t)g * Dv + tid];
    __shared__ float s[256];
    s[tid] = v * v;
    __syncthreads();
    for (int st = 128; st > 0; st >>= 1) {
        if (tid < st) s[tid] += s[tid + st];
        __syncthreads();
    }
    if (tid == 0) g_nn[g] = s[0];
}

// ---------------------------------------------------------------------------
// K0b: warp-per-row prep. wz = z * decay^(T-1-t) * mask + row norms.
// Time weight via powf(0.999f, k) (matches reference's f32 power bitwise),
// computed in lane 0, broadcast by shuffle. Shuffle-only reduction.
// ---------------------------------------------------------------------------
__global__ __launch_bounds__(256) void k_prep(const float* __restrict__ z,
                                              const float* __restrict__ mask) {
    int warp = threadIdx.x >> 5, lane = threadIdx.x & 31;
    int r = blockIdx.x * 8 + warp;
    float tw = 0.f;
    if (lane == 0) {
        int t = r % Tv;
        tw = powf(0.999f, (float)(Tv - 1 - t));
    }
    tw = __shfl_sync(0xFFFFFFFFu, tw, 0);
    float m = mask[r];
    const float* zp = z + (size_t)r * Dv + lane * 8;
    float* wp = g_wz + (size_t)r * Dv + lane * 8;
    float4 a = *(const float4*)zp;
    float4 b = *(const float4*)(zp + 4);
    a.x = (a.x * tw) * m; a.y = (a.y * tw) * m; a.z = (a.z * tw) * m; a.w = (a.w * tw) * m;
    b.x = (b.x * tw) * m; b.y = (b.y * tw) * m; b.z = (b.z * tw) * m; b.w = (b.w * tw) * m;
    *(float4*)wp = a;
    *(float4*)(wp + 4) = b;
    float s = a.x * a.x + a.y * a.y + a.z * a.z + a.w * a.w
            + b.x * b.x + b.y * b.y + b.z * b.z + b.w * b.w;
#pragma unroll
    for (int off = 16; off > 0; off >>= 1)
        s += __shfl_xor_sync(0xFFFFFFFFu, s, off);
    if (lane == 0) g_rown[r] = s;
}

// ---------------------------------------------------------------------------
// K1: bf16 mma.sync m16n8k16 GEMM, fragment-major smem layout.
// BM=128, BN=64, 256 threads = 8 warps (4M x 2N), warp tile 32x32.
// Register prefetch, single smem buffer. Fused epilogue writes
// unnormalized u = 1/(1+sqrt(d2)) into the q region of d_out.
// ---------------------------------------------------------------------------
__global__ __launch_bounds__(256, 2) void k_gemm_bf(const float* __restrict__ nodes,
                                                    float* __restrict__ out) {
    __shared__ uint32_t sA[2048];   // 128 rows x 16 kpairs, fragment-major (8KB)
    __shared__ uint32_t sB[1024];   // 64 n x 16 kpairs, fragment-major (4KB)
    __shared__ float s_rn[128];
    __shared__ float s_nn[64];

    int tid = threadIdx.x;
    int lane = tid & 31, wid = tid >> 5;
    int g4 = lane >> 2, tg = lane & 3;
    int wm = wid & 3, wn = wid >> 2;
    int rowBase = blockIdx.x * 128;
    int colBase = blockIdx.y * 64;

    int lr = tid >> 3;          // 0..31
    int seg = tid & 7;          // k segment (4 floats each)

    const float* Ag = g_wz  + (size_t)(rowBase + lr) * Dv + seg * 4;
    const float* Bg = nodes + (size_t)(colBase + lr) * Dv + seg * 4;

    // precompute store word-indices (chunk-invariant)
    int aI[4][2], bI[2][2];
#pragma unroll
    for (int i = 0; i < 4; i++) {
        aI[i][0] = aIdx(lr + i * 32, seg * 2);
        aI[i][1] = aIdx(lr + i * 32, seg * 2 + 1);
    }
#pragma unroll
    for (int i = 0; i < 2; i++) {
        bI[i][0] = bIdx(lr + i * 32, seg * 2);
        bI[i][1] = bIdx(lr + i * 32, seg * 2 + 1);
    }

    float acc[2][4][4];
#pragma unroll
    for (int mi = 0; mi < 2; mi++)
#pragma unroll
        for (int ni = 0; ni < 4; ni++)
#pragma unroll
            for (int k = 0; k < 4; k++) acc[mi][ni][k] = 0.f;

    float4 pa[4], pb[2];
#pragma unroll
    for (int i = 0; i < 4; i++) pa[i] = *(const float4*)(Ag + (size_t)i * 32 * Dv);
#pragma unroll
    for (int i = 0; i < 2; i++) pb[i] = *(const float4*)(Bg + (size_t)i * 32 * Dv);

    for (int ch = 0; ch < NCHUNK; ch++) {
        // stage prefetched registers into fragment-major smem
#pragma unroll
        for (int i = 0; i < 4; i++) {
            sA[aI[i][0]] = bfpack(pa[i].x, pa[i].y);
            sA[aI[i][1]] = bfpack(pa[i].z, pa[i].w);
        }
#pragma unroll
        for (int i = 0; i < 2; i++) {
            sB[bI[i][0]] = bfpack(pb[i].x, pb[i].y);
            sB[bI[i][1]] = bfpack(pb[i].z, pb[i].w);
        }
        __syncthreads();

        if (ch + 1 < NCHUNK) {
            const float* Ap2 = Ag + (ch + 1) * KCH;
            const float* Bp2 = Bg + (ch + 1) * KCH;
#pragma unroll
            for (int i = 0; i < 4; i++) pa[i] = *(const float4*)(Ap2 + (size_t)i * 32 * Dv);
#pragma unroll
            for (int i = 0; i < 2; i++) pb[i] = *(const float4*)(Bp2 + (size_t)i * 32 * Dv);
        }

#pragma unroll
        for (int kk = 0; kk < 2; kk++) {
            uint4 af[2], bv[2];
#pragma unroll
            for (int mi = 0; mi < 2; mi++)
                af[mi] = *(const uint4*)&sA[((wm * 2 + mi) * 2 + kk) * 128 + g4 * 16 + tg * 4];
#pragma unroll
            for (int nh = 0; nh < 2; nh++)
                bv[nh] = *(const uint4*)&sB[(wn * 2 + kk) * 256 + nh * 128 + g4 * 16 + tg * 4];
#pragma unroll
            for (int mi = 0; mi < 2; mi++) {
                const uint32_t* ar = (const uint32_t*)&af[mi];
                mma16(acc[mi][0], ar, bv[0].x, bv[0].y);
                mma16(acc[mi][1], ar, bv[0].z, bv[0].w);
                mma16(acc[mi][2], ar, bv[1].x, bv[1].y);
                mma16(acc[mi][3], ar, bv[1].z, bv[1].w);
            }
        }
        __syncthreads();
    }

    // stage norms
    if (tid < 128) s_rn[tid] = g_rown[rowBase + tid];
    if (tid < 64)  s_nn[tid] = g_nn[colBase + tid];
    __syncthreads();

    float* q = out + OFF_Q;
#pragma unroll
    for (int mi = 0; mi < 2; mi++) {
#pragma unroll
        for (int h = 0; h < 2; h++) {
            int r = wm * 32 + mi * 16 + g4 + h * 8;
            float rn = s_rn[r];
            size_t grow = (size_t)(rowBase + r) * Gv + colBase;
#pragma unroll
            for (int ni = 0; ni < 4; ni++) {
                int c = wn * 32 + ni * 8 + tg * 2;
                float c0 = acc[mi][ni][h * 2 + 0];
                float c1 = acc[mi][ni][h * 2 + 1];
                float d20 = fmaxf((rn - 2.f * c0) + s_nn[c],     1e-12f);
                float d21 = fmaxf((rn - 2.f * c1) + s_nn[c + 1], 1e-12f);
                float2 o;
                o.x = 1.f / (1.f + sqrtf(d20));
                o.y = 1.f / (1.f + sqrtf(d21));
                *(float2*)(q + grow + c) = o;
            }
        }
    }
}

// ---------------------------------------------------------------------------
// K2: per-row pass. Warp-shuffle sum + argmax; fp64 exact refinement of the
// argmin over near-tie candidates (margin sized for bf16 GEMM noise), with a
// full-scan fallback if the candidate buffer overflows (never silently wrong).
// ---------------------------------------------------------------------------
__global__ __launch_bounds__(256) void k_row(const float* __restrict__ z,
                                             const float* __restrict__ mask,
                                             const float* __restrict__ nodes,
                                             float* __restrict__ out) {
    int r = blockIdx.x;
    int tid = threadIdx.x;
    int lane = tid & 31, warp = tid >> 5;
    float* qptr = out + OFF_Q + (size_t)r * Gv;

    float4 u4 = ((const float4*)qptr)[tid];
    float4 uo = u4;
    float lsum = (u4.x + u4.y) + (u4.z + u4.w);
    float bv = u4.x; int bi = tid * 4;
    if (u4.y > bv) { bv = u4.y; bi = tid * 4 + 1; }
    if (u4.z > bv) { bv = u4.z; bi = tid * 4 + 2; }
    if (u4.w > bv) { bv = u4.w; bi = tid * 4 + 3; }

#pragma unroll
    for (int off = 16; off > 0; off >>= 1) {
        float os = __shfl_xor_sync(0xFFFFFFFFu, lsum, off);
        float ov = __shfl_xor_sync(0xFFFFFFFFu, bv, off);
        int   oi = __shfl_xor_sync(0xFFFFFFFFu, bi, off);
        lsum += os;
        if (ov > bv || (ov == bv && oi < bi)) { bv = ov; bi = oi; }
    }

    __shared__ float sWs[8], sWv[8];
    __shared__ int   sWi[8];
    __shared__ float sSum, sMax;
    __shared__ int   sBmu;
    if (lane == 0) { sWs[warp] = lsum; sWv[warp] = bv; sWi[warp] = bi; }
    __syncthreads();
    if (tid == 0) {
        float ts = 0.f, tv = -1.f; int ti = 0;
#pragma unroll
        for (int w = 0; w < 8; w++) {
            ts += sWs[w];
            if (sWv[w] > tv || (sWv[w] == tv && sWi[w] < ti)) { tv = sWv[w]; ti = sWi[w]; }
        }
        sSum = ts; sMax = tv; sBmu = ti;
    }
    __syncthreads();
    float inv = 1.f / sSum;
    float umax = sMax;
    int bmu = sBmu;

    u4.x *= inv; u4.y *= inv; u4.z *= inv; u4.w *= inv;
    ((float4*)qptr)[tid] = u4;

    // ---- exact argmin refinement for near-ties ----
    float dist1 = 1.f / umax - 1.f;
    float ut = 1.f / (1.f + dist1 + REFINE_MARGIN);

    __shared__ int sCand[MAX_CAND];
    __shared__ int sCnt;
    __shared__ double sWd[8];
    __shared__ double sBest;
    if (tid == 0) sCnt = 0;
    __syncthreads();
    {
        float uu[4] = {uo.x, uo.y, uo.z, uo.w};
#pragma unroll
        for (int j = 0; j < 4; j++) {
            if (uu[j] >= ut) {
                int slot = atomicAdd(&sCnt, 1);
                if (slot < MAX_CAND) sCand[slot] = tid * 4 + j;
            }
        }
    }
    __syncthreads();
    bool overflow = sCnt > MAX_CAND;
    int ncand = overflow ? Gv : sCnt;

    if (ncand > 1) {
        float wzv = g_wz[(size_t)r * Dv + tid];
        double bestd = 1e300;
        int besti = Gv;
        for (int c = 0; c < ncand; c++) {
            int g = overflow ? c : sCand[c];
            double diff = (double)wzv - (double)nodes[(size_t)g * Dv + tid];
            double d = diff * diff;
#pragma unroll
            for (int off = 16; off > 0; off >>= 1)
                d += __shfl_xor_sync(0xFFFFFFFFu, d, off);
            if (lane == 0) sWd[warp] = d;
            __syncthreads();
            if (tid == 0) {
                double s = 0.0;
#pragma unroll
                for (int w = 0; w < 8; w++) s += sWd[w];
                sBest = s;
            }
            __syncthreads();
            double d2c = sBest;
            if (d2c < bestd || (d2c == bestd && g < besti)) { bestd = d2c; besti = g; }
        }
        bmu = besti;
    }

    // som_z
    float zz = z[(size_t)r * Dv + tid];
    float m = mask[r];
    float nv = nodes[(size_t)bmu * Dv + tid];
    out[(size_t)r * Dv + tid] = zz + 0.1f * (nv - zz) * m;

    if (tid == 0) {
        out[OFF_BMU + r] = (float)bmu;
        float* kc = out + OFF_KC;
        kc[(size_t)r * 2 + 0] = (float)(bmu / GWv);
        kc[(size_t)r * 2 + 1] = (float)(bmu % GWv);
    }
}

// ---------------------------------------------------------------------------
extern "C" void kernel_launch(void* const* d_in, const int* in_sizes, int n_in,
                              void* d_out, int out_size) {
    (void)in_sizes; (void)n_in; (void)out_size;
    const float* z     = (const float*)d_in[0];
    const float* mask  = (const float*)d_in[1];
    const float* nodes = (const float*)d_in[2];
    float* out = (float*)d_out;

    k_node_norm<<<Gv, 256>>>(nodes);
    k_prep<<<BT / 8, 256>>>(z, mask);
    dim3 grid(BT / 128, Gv / 64);
    k_gemm_bf<<<grid, 256>>>(nodes, out);
    k_row<<<BT, 256>>>(z, mask, nodes, out);
}

// round 10
// speedup vs baseline: 2.6180x; 1.0911x over previous
#include <cuda_runtime.h>
#include <math.h>
#include <stdint.h>

// Problem constants (fixed by the dataset)
#define Bv 16
#define Tv 3072
#define Dv 256
#define GHv 32
#define GWv 32
#define Gv 1024
#define BT (Bv * Tv)          // 49152

// Output layout: concat of [som_z (BT*Dv)] [q (BT*Gv)] [bmu (BT)] [k_coord (BT*2)]
#define OFF_Q   ((size_t)BT * Dv)
#define OFF_BMU (OFF_Q + (size_t)BT * Gv)
#define OFF_KC  (OFF_BMU + (size_t)BT)

// Exact-argmin refinement margin (dist units) and candidate cap.
#define REFINE_MARGIN 1.5e-2f
#define MAX_CAND 64

// GEMM tiling: BM=128, BN=128, K chunks of 32
#define KCH 32
#define NCHUNK (Dv / KCH)      // 8

// Scratch (static device allocation — allowed; no cudaMalloc)
__device__ float g_wz[(size_t)BT * Dv];   // weighted z (time decay * mask)
__device__ float g_rown[BT];              // ||wz_row||^2
__device__ float g_nn[Gv];                // ||node||^2

// ---------------------------------------------------------------------------
// helpers
// ---------------------------------------------------------------------------
__device__ __forceinline__ uint32_t bfpack(float lo, float hi) {
    uint32_t r;
    asm("cvt.rn.bf16x2.f32 %0, %1, %2;" : "=r"(r) : "f"(hi), "f"(lo));
    return r;
}

__device__ __forceinline__ void mma16(float* c, const uint32_t* a,
                                      uint32_t b0, uint32_t b1) {
    asm volatile(
        "mma.sync.aligned.m16n8k16.row.col.f32.bf16.bf16.f32 "
        "{%0,%1,%2,%3}, {%4,%5,%6,%7}, {%8,%9}, {%0,%1,%2,%3};"
        : "+f"(c[0]), "+f"(c[1]), "+f"(c[2]), "+f"(c[3])
        : "r"(a[0]), "r"(a[1]), "r"(a[2]), "r"(a[3]), "r"(b0), "r"(b1));
}

// Fragment-major word index for A (128 rows x 16 kpairs per chunk).
__device__ __forceinline__ int aIdx(int row, int p) {
    int wm = row >> 5, mi = (row >> 4) & 1, hi = (row >> 3) & 1, g4 = row & 7;
    int kk = p >> 3, w8 = p & 7, tg = w8 & 3, poff = w8 >> 2;
    return (((wm * 2 + mi) * 2 + kk) * 128) + g4 * 16 + tg * 4 + poff * 2 + hi;
}

// Fragment-major word index for B (128 n x 16 kpairs per chunk).
// wn in 0..3 (warp n-tile of 32), region stride 256 words.
__device__ __forceinline__ int bIdx(int n, int p) {
    int wn = n >> 5, ni = (n >> 3) & 3, g4 = n & 7;
    int nh = ni >> 1, nl = ni & 1;
    int kk = p >> 3, w8 = p & 7, tg = w8 & 3, b01 = w8 >> 2;
    return ((wn * 2 + kk) * 256) + nh * 128 + g4 * 16 + tg * 4 + nl * 2 + b01;
}

// ---------------------------------------------------------------------------
// K0a: node squared norms.
// ---------------------------------------------------------------------------
__global__ void k_node_norm(const float* __restrict__ nodes) {
    int g = blockIdx.x;
    int tid = threadIdx.x;
    float v = nodes[(size_t)g * Dv + tid];
    __shared__ float s[256];
    s[tid] = v * v;
    __syncthreads();
    for (int st = 128; st > 0; st >>= 1) {
        if (tid < st) s[tid] += s[tid + st];
        __syncthreads();
    }
    if (tid == 0) g_nn[g] = s[0];
}

// ---------------------------------------------------------------------------
// K0b: warp-per-row prep. wz = z * decay^(T-1-t) * mask + row norms.
// ---------------------------------------------------------------------------
__global__ __launch_bounds__(256) void k_prep(const float* __restrict__ z,
                                              const float* __restrict__ mask) {
    int warp = threadIdx.x >> 5, lane = threadIdx.x & 31;
    int r = blockIdx.x * 8 + warp;
    float tw = 0.f;
    if (lane == 0) {
        int t = r % Tv;
        tw = powf(0.999f, (float)(Tv - 1 - t));
    }
    tw = __shfl_sync(0xFFFFFFFFu, tw, 0);
    float m = mask[r];
    const float* zp = z + (size_t)r * Dv + lane * 8;
    float* wp = g_wz + (size_t)r * Dv + lane * 8;
    float4 a = *(const float4*)zp;
    float4 b = *(const float4*)(zp + 4);
    a.x = (a.x * tw) * m; a.y = (a.y * tw) * m; a.z = (a.z * tw) * m; a.w = (a.w * tw) * m;
    b.x = (b.x * tw) * m; b.y = (b.y * tw) * m; b.z = (b.z * tw) * m; b.w = (b.w * tw) * m;
    *(float4*)wp = a;
    *(float4*)(wp + 4) = b;
    float s = a.x * a.x + a.y * a.y + a.z * a.z + a.w * a.w
            + b.x * b.x + b.y * b.y + b.z * b.z + b.w * b.w;
#pragma unroll
    for (int off = 16; off > 0; off >>= 1)
        s += __shfl_xor_sync(0xFFFFFFFFu, s, off);
    if (lane == 0) g_rown[r] = s;
}

// ---------------------------------------------------------------------------
// K1: bf16 mma.sync m16n8k16 GEMM, fragment-major smem, DOUBLE-BUFFERED.
// BM=128, BN=128, 512 threads = 16 warps (4M x 4N), warp tile 32x32.
// Fused epilogue writes unnormalized u = 1/(1+sqrt(d2)) into q.
// ---------------------------------------------------------------------------
__global__ __launch_bounds__(512, 2) void k_gemm_bf(const float* __restrict__ nodes,
                                                    float* __restrict__ out) {
    __shared__ uint32_t sA[2][2048];   // per buffer: 128 rows x 16 kpairs (8KB)
    __shared__ uint32_t sB[2][2048];   // per buffer: 128 n   x 16 kpairs (8KB)
    __shared__ float s_rn[128];
    __shared__ float s_nn[128];

    int tid = threadIdx.x;
    int lane = tid & 31, wid = tid >> 5;
    int g4 = lane >> 2, tg = lane & 3;
    int wm = wid & 3, wn = wid >> 2;           // 4 x 4 warp grid
    int rowBase = blockIdx.x * 128;
    int colBase = blockIdx.y * 128;

    int lr = tid >> 3;          // 0..63
    int seg = tid & 7;          // k segment (4 floats)

    const float* Ag = g_wz  + (size_t)(rowBase + lr) * Dv + seg * 4;
    const float* Bg = nodes + (size_t)(colBase + lr) * Dv + seg * 4;

    float acc[2][4][4];
#pragma unroll
    for (int mi = 0; mi < 2; mi++)
#pragma unroll
        for (int ni = 0; ni < 4; ni++)
#pragma unroll
            for (int k = 0; k < 4; k++) acc[mi][ni][k] = 0.f;

    float4 pa[2], pb[2];

    // global load of one chunk into registers
    auto gload = [&](int ch) {
#pragma unroll
        for (int i = 0; i < 2; i++)
            pa[i] = *(const float4*)(Ag + ch * KCH + (size_t)i * 64 * Dv);
#pragma unroll
        for (int i = 0; i < 2; i++)
            pb[i] = *(const float4*)(Bg + ch * KCH + (size_t)i * 64 * Dv);
    };
    // stage registers into fragment-major smem buffer
    auto stage = [&](int buf) {
#pragma unroll
        for (int i = 0; i < 2; i++) {
            int row = lr + i * 64;
            sA[buf][aIdx(row, seg * 2)]     = bfpack(pa[i].x, pa[i].y);
            sA[buf][aIdx(row, seg * 2 + 1)] = bfpack(pa[i].z, pa[i].w);
        }
#pragma unroll
        for (int i = 0; i < 2; i++) {
            int n = lr + i * 64;
            sB[buf][bIdx(n, seg * 2)]     = bfpack(pb[i].x, pb[i].y);
            sB[buf][bIdx(n, seg * 2 + 1)] = bfpack(pb[i].z, pb[i].w);
        }
    };

    gload(0);
    stage(0);
    __syncthreads();

    for (int ch = 0; ch < NCHUNK; ch++) {
        int cur = ch & 1;
        if (ch + 1 < NCHUNK) gload(ch + 1);

#pragma unroll
        for (int kk = 0; kk < 2; kk++) {
            uint4 af[2], bv[2];
#pragma unroll
            for (int mi = 0; mi < 2; mi++)
                af[mi] = *(const uint4*)&sA[cur][((wm * 2 + mi) * 2 + kk) * 128 + g4 * 16 + tg * 4];
#pragma unroll
            for (int nh = 0; nh < 2; nh++)
                bv[nh] = *(const uint4*)&sB[cur][(wn * 2 + kk) * 256 + nh * 128 + g4 * 16 + tg * 4];
#pragma unroll
            for (int mi = 0; mi < 2; mi++) {
                const uint32_t* ar = (const uint32_t*)&af[mi];
                mma16(acc[mi][0], ar, bv[0].x, bv[0].y);
                mma16(acc[mi][1], ar, bv[0].z, bv[0].w);
                mma16(acc[mi][2], ar, bv[1].x, bv[1].y);
                mma16(acc[mi][3], ar, bv[1].z, bv[1].w);
            }
        }

        if (ch + 1 < NCHUNK) {
            stage(1 - cur);
            __syncthreads();
        }
    }

    // stage norms
    if (tid < 128) {
        s_rn[tid] = g_rown[rowBase + tid];
        s_nn[tid] = g_nn[colBase + tid];
    }
    __syncthreads();

    float* q = out + OFF_Q;
#pragma unroll
    for (int mi = 0; mi < 2; mi++) {
#pragma unroll
        for (int h = 0; h < 2; h++) {
            int r = wm * 32 + mi * 16 + g4 + h * 8;
            float rn = s_rn[r];
            size_t grow = (size_t)(rowBase + r) * Gv + colBase;
#pragma unroll
            for (int ni = 0; ni < 4; ni++) {
                int c = wn * 32 + ni * 8 + tg * 2;
                float c0 = acc[mi][ni][h * 2 + 0];
                float c1 = acc[mi][ni][h * 2 + 1];
                float d20 = fmaxf((rn - 2.f * c0) + s_nn[c],     1e-12f);
                float d21 = fmaxf((rn - 2.f * c1) + s_nn[c + 1], 1e-12f);
                float2 o;
                o.x = 1.f / (1.f + sqrtf(d20));
                o.y = 1.f / (1.f + sqrtf(d21));
                *(float2*)(q + grow + c) = o;
            }
        }
    }
}

// ---------------------------------------------------------------------------
// K2: per-row pass (unchanged from R9; proven).
// ---------------------------------------------------------------------------
__global__ __launch_bounds__(256) void k_row(const float* __restrict__ z,
                                             const float* __restrict__ mask,
                                             const float* __restrict__ nodes,
                                             float* __restrict__ out) {
    int r = blockIdx.x;
    int tid = threadIdx.x;
    int lane = tid & 31, warp = tid >> 5;
    float* qptr = out + OFF_Q + (size_t)r * Gv;

    float4 u4 = ((const float4*)qptr)[tid];
    float4 uo = u4;
    float lsum = (u4.x + u4.y) + (u4.z + u4.w);
    float bv = u4.x; int bi = tid * 4;
    if (u4.y > bv) { bv = u4.y; bi = tid * 4 + 1; }
    if (u4.z > bv) { bv = u4.z; bi = tid * 4 + 2; }
    if (u4.w > bv) { bv = u4.w; bi = tid * 4 + 3; }

#pragma unroll
    for (int off = 16; off > 0; off >>= 1) {
        float os = __shfl_xor_sync(0xFFFFFFFFu, lsum, off);
        float ov = __shfl_xor_sync(0xFFFFFFFFu, bv, off);
        int   oi = __shfl_xor_sync(0xFFFFFFFFu, bi, off);
        lsum += os;
        if (ov > bv || (ov == bv && oi < bi)) { bv = ov; bi = oi; }
    }

    __shared__ float sWs[8], sWv[8];
    __shared__ int   sWi[8];
    __shared__ float sSum, sMax;
    __shared__ int   sBmu;
    if (lane == 0) { sWs[warp] = lsum; sWv[warp] = bv; sWi[warp] = bi; }
    __syncthreads();
    if (tid == 0) {
        float ts = 0.f, tv = -1.f; int ti = 0;
#pragma unroll
        for (int w = 0; w < 8; w++) {
            ts += sWs[w];
            if (sWv[w] > tv || (sWv[w] == tv && sWi[w] < ti)) { tv = sWv[w]; ti = sWi[w]; }
        }
        sSum = ts; sMax = tv; sBmu = ti;
    }
    __syncthreads();
    float inv = 1.f / sSum;
    float umax = sMax;
    int bmu = sBmu;

    u4.x *= inv; u4.y *= inv; u4.z *= inv; u4.w *= inv;
    ((float4*)qptr)[tid] = u4;

    // ---- exact argmin refinement for near-ties ----
    float dist1 = 1.f / umax - 1.f;
    float ut = 1.f / (1.f + dist1 + REFINE_MARGIN);

    __shared__ int sCand[MAX_CAND];
    __shared__ int sCnt;
    __shared__ double sWd[8];
    __shared__ double sBest;
    if (tid == 0) sCnt = 0;
    __syncthreads();
    {
        float uu[4] = {uo.x, uo.y, uo.z, uo.w};
#pragma unroll
        for (int j = 0; j < 4; j++) {
            if (uu[j] >= ut) {
                int slot = atomicAdd(&sCnt, 1);
                if (slot < MAX_CAND) sCand[slot] = tid * 4 + j;
            }
        }
    }
    __syncthreads();
    bool overflow = sCnt > MAX_CAND;
    int ncand = overflow ? Gv : sCnt;

    if (ncand > 1) {
        float wzv = g_wz[(size_t)r * Dv + tid];
        double bestd = 1e300;
        int besti = Gv;
        for (int c = 0; c < ncand; c++) {
            int g = overflow ? c : sCand[c];
            double diff = (double)wzv - (double)nodes[(size_t)g * Dv + tid];
            double d = diff * diff;
#pragma unroll
            for (int off = 16; off > 0; off >>= 1)
                d += __shfl_xor_sync(0xFFFFFFFFu, d, off);
            if (lane == 0) sWd[warp] = d;
            __syncthreads();
            if (tid == 0) {
                double s = 0.0;
#pragma unroll
                for (int w = 0; w < 8; w++) s += sWd[w];
                sBest = s;
            }
            __syncthreads();
            double d2c = sBest;
            if (d2c < bestd || (d2c == bestd && g < besti)) { bestd = d2c; besti = g; }
        }
        bmu = besti;
    }

    // som_z
    float zz = z[(size_t)r * Dv + tid];
    float m = mask[r];
    float nv = nodes[(size_t)bmu * Dv + tid];
    out[(size_t)r * Dv + tid] = zz + 0.1f * (nv - zz) * m;

    if (tid == 0) {
        out[OFF_BMU + r] = (float)bmu;
        float* kc = out + OFF_KC;
        kc[(size_t)r * 2 + 0] = (float)(bmu / GWv);
        kc[(size_t)r * 2 + 1] = (float)(bmu % GWv);
    }
}

// ---------------------------------------------------------------------------
extern "C" void kernel_launch(void* const* d_in, const int* in_sizes, int n_in,
                              void* d_out, int out_size) {
    (void)in_sizes; (void)n_in; (void)out_size;
    const float* z     = (const float*)d_in[0];
    const float* mask  = (const float*)d_in[1];
    const float* nodes = (const float*)d_in[2];
    float* out = (float*)d_out;

    k_node_norm<<<Gv, 256>>>(nodes);
    k_prep<<<BT / 8, 256>>>(z, mask);
    dim3 grid(BT / 128, Gv / 128);
    k_gemm_bf<<<grid, 512>>>(nodes, out);
    k_row<<<BT, 256>>>(z, mask, nodes, out);
}